// round 7
// baseline (speedup 1.0000x reference)
#include <cuda_runtime.h>
#include <math.h>

// Problem constants
#define BB 32
#define SS 4096
#define HH 1024
#define NSPLIT 8                   // splits of S per batch -> 256 blocks
#define S_SPLIT (SS / NSPLIT)      // 512 rows per block
#define WARPS 8
#define ROWS_PER_WARP (S_SPLIT / WARPS)  // 64
#define F4_PER_ROW (HH / 4)        // 256
#define F4_PER_B (HH / 4)          // 256

// Scratch for split-K partials (no runtime allocation allowed).
// energy = tanh(.) in [-1,1] => exp(energy) in [1/e, e]: no max-subtraction
// needed; softmax(e) == exp(e)/sum(exp(e)) exactly.
__device__ float g_cpart[BB * NSPLIT * HH];   // 1 MiB partial contexts
__device__ float g_l[BB * NSPLIT];            // partial normalizers

// ---------------------------------------------------------------------------
// Pass 1: warp-per-row streaming. Lane ln owns float4 column slices j*32+ln,
// j=0..7. Per row: 8 independent LDG.128 -> in-register dot -> shfl butterfly
// reduce -> p = exp(tanh(s)) (fast-math, all lanes) -> FMA accumulate.
// NO block barriers in the main loop; single end-of-kernel smem combine.
// ---------------------------------------------------------------------------
__global__ __launch_bounds__(256, 2)
void attn_pass1(const float* __restrict__ x, const float* __restrict__ w) {
    const int blk = blockIdx.x;
    const int b   = blk / NSPLIT;
    const int sp  = blk % NSPLIT;
    const int t   = threadIdx.x;
    const int wd  = t >> 5;
    const int ln  = t & 31;

    // w fragment in registers (8 float4 = 32 regs)
    const float4* __restrict__ w4p = (const float4*)w;
    float4 wf[8];
    #pragma unroll
    for (int j = 0; j < 8; j++) wf[j] = w4p[j * 32 + ln];

    const float4* __restrict__ xbase =
        (const float4*)(x + ((size_t)b * SS + (size_t)sp * S_SPLIT) * HH);

    float4 c[8];
    #pragma unroll
    for (int j = 0; j < 8; j++) c[j] = make_float4(0.f, 0.f, 0.f, 0.f);
    float l = 0.f;

    for (int i = 0; i < ROWS_PER_WARP; i++) {
        const int row = i * WARPS + wd;          // adjacent warps -> adjacent rows
        const float4* __restrict__ xrow = xbase + (size_t)row * F4_PER_ROW;

        float4 xr[8];
        #pragma unroll
        for (int j = 0; j < 8; j++) xr[j] = __ldcs(&xrow[j * 32 + ln]);

        float s = 0.f;
        #pragma unroll
        for (int j = 0; j < 8; j++)
            s += xr[j].x * wf[j].x + xr[j].y * wf[j].y
               + xr[j].z * wf[j].z + xr[j].w * wf[j].w;

        #pragma unroll
        for (int off = 16; off > 0; off >>= 1)
            s += __shfl_xor_sync(0xffffffffu, s, off);

        // p = exp(tanh(s)); tanh via exp: (e^{2s}-1)/(e^{2s}+1). |s| <= ~15
        // here so e^{2s} stays finite in fp32.
        const float t2 = __expf(2.f * s);
        const float th = (t2 - 1.f) / (t2 + 1.f);
        const float p  = __expf(th);

        l += p;
        #pragma unroll
        for (int j = 0; j < 8; j++) {
            c[j].x += p * xr[j].x;
            c[j].y += p * xr[j].y;
            c[j].z += p * xr[j].z;
            c[j].w += p * xr[j].w;
        }
    }

    // Combine 8 warp accumulators (fixed order -> deterministic).
    __shared__ float4 sacc[WARPS][F4_PER_ROW];   // 32 KiB
    __shared__ float  sl[WARPS];
    #pragma unroll
    for (int j = 0; j < 8; j++) sacc[wd][j * 32 + ln] = c[j];
    if (ln == 0) sl[wd] = l;
    __syncthreads();

    float4 r = sacc[0][t];
    #pragma unroll
    for (int g = 1; g < WARPS; g++) {
        const float4 v = sacc[g][t];
        r.x += v.x; r.y += v.y; r.z += v.z; r.w += v.w;
    }
    const int pidx = b * NSPLIT + sp;
    ((float4*)g_cpart)[(size_t)pidx * F4_PER_B + t] = r;
    if (t == 0) {
        float L = 0.f;
        #pragma unroll
        for (int g = 0; g < WARPS; g++) L += sl[g];
        g_l[pidx] = L;
    }
}

// ---------------------------------------------------------------------------
// Pass 2: flat combine of the 8 split partials per batch (1 MiB total).
// 8192 threads, one float4 output slice each; 8 independent LDG.128/thread.
// ---------------------------------------------------------------------------
__global__ __launch_bounds__(128)
void attn_pass2(float* __restrict__ out) {
    const int gid = blockIdx.x * 128 + threadIdx.x;
    const int b   = gid >> 8;          // / F4_PER_B
    const int f4  = gid & (F4_PER_B - 1);

    float L = 0.f;
    #pragma unroll
    for (int p = 0; p < NSPLIT; p++) L += g_l[b * NSPLIT + p];

    float4 acc = make_float4(0.f, 0.f, 0.f, 0.f);
    #pragma unroll
    for (int p = 0; p < NSPLIT; p++) {
        const float4 cp =
            ((const float4*)g_cpart)[(size_t)(b * NSPLIT + p) * F4_PER_B + f4];
        acc.x += cp.x; acc.y += cp.y; acc.z += cp.z; acc.w += cp.w;
    }
    const float inv = 1.f / L;
    acc.x *= inv; acc.y *= inv; acc.z *= inv; acc.w *= inv;
    ((float4*)out)[(size_t)b * F4_PER_B + f4] = acc;
}

extern "C" void kernel_launch(void* const* d_in, const int* in_sizes, int n_in,
                              void* d_out, int out_size) {
    const float* x = (const float*)d_in[0];   // [B, S, H] fp32
    const float* w = (const float*)d_in[1];   // [H] fp32
    float* out = (float*)d_out;               // [B, H] fp32
    (void)in_sizes; (void)n_in; (void)out_size;

    attn_pass1<<<BB * NSPLIT, 256>>>(x, w);
    attn_pass2<<<(BB * F4_PER_B) / 128, 128>>>(out);
}